// round 10
// baseline (speedup 1.0000x reference)
#include <cuda_runtime.h>
#include <cuda_fp16.h>
#include <cstdint>

// FourierKAN fused feature-gen + mma.sync fp16 GEMM (compute_103-safe).
// y[b,j] = sum_{i,g} cos((g+1)x_bi)C0[j,i,g] + sin((g+1)x_bi)C1[j,i,g] + bias[j]
// k layout: k = i*64 + 2*g + trig  (even k = cos, odd k = sin)
// CTA tile 128x64, 8 warps (4m x 2n), warp 32x32, split-K x8, 3 CTAs/SM.
// 1024 CTAs on 444 residency slots; 6 warps/SMSP for latency hiding.

#define IN_DIM   256
#define OUT_DIM  256
#define KTOT     (IN_DIM * 64)
#define BM       128
#define BN       64
#define ISPLIT   8
#define IPER     (IN_DIM / ISPLIT)   // 32
#define M_MAX    4096

#define LDRB     144                 // 72-half row stride: 16B aligned, LDSM conflict-free

#define OFF_A0   0
#define OFF_A1   18432               // 128*144
#define OFF_B0   36864               // 64*144 = 9216 per B buffer
#define OFF_B1   46080
#define SMEM_BYTES 55296             // 54 KB -> 3 CTAs/SM (162 KB)

__device__ __half g_Wt[OUT_DIM * KTOT];              // 8.4 MB (L2-resident)
__device__ float  g_part[ISPLIT * M_MAX * OUT_DIM];  // 32 MB split-K partials

__device__ __forceinline__ unsigned sptr(const void* p) {
    return (unsigned)__cvta_generic_to_shared(p);
}

#define CP_ASYNC16(dst, src) \
    asm volatile("cp.async.cg.shared.global [%0], [%1], 16;\n" :: "r"(dst), "l"(src))
#define CP_COMMIT() asm volatile("cp.async.commit_group;\n" ::)
#define CP_WAIT0()  asm volatile("cp.async.wait_group 0;\n" ::)

__device__ __forceinline__ void mma16816(float c[4], const unsigned a[4], const unsigned* b) {
    asm volatile(
        "mma.sync.aligned.m16n8k16.row.col.f32.f16.f16.f32 "
        "{%0,%1,%2,%3}, {%4,%5,%6,%7}, {%8,%9}, {%0,%1,%2,%3};\n"
        : "+f"(c[0]), "+f"(c[1]), "+f"(c[2]), "+f"(c[3])
        : "r"(a[0]), "r"(a[1]), "r"(a[2]), "r"(a[3]), "r"(b[0]), "r"(b[1]));
}
__device__ __forceinline__ void ldsm_x4(unsigned r[4], unsigned addr) {
    asm volatile("ldmatrix.sync.aligned.m8n8.x4.shared.b16 {%0,%1,%2,%3}, [%4];\n"
                 : "=r"(r[0]), "=r"(r[1]), "=r"(r[2]), "=r"(r[3]) : "r"(addr));
}

// ---------------------------------------------------------------------------
// Prep: coeffs fp32 [2][out][in][grid] -> fp16 g_Wt[j][i*64 + 2g + trig]
// ---------------------------------------------------------------------------
__global__ void __launch_bounds__(256) prep_coeffs_kernel(const float* __restrict__ C) {
    unsigned u = blockIdx.x * blockDim.x + threadIdx.x;   // 0 .. 2^19-1
    const float4* C4 = reinterpret_cast<const float4*>(C);
    float4 c = C4[u];                 // cos coeffs, g = 4a..4a+3
    float4 s = C4[u + (1u << 19)];    // sin coeffs
    unsigned a = u & 7, i = (u >> 3) & 255, j = u >> 11;
    __half2 h0 = __floats2half2_rn(c.x, s.x);
    __half2 h1 = __floats2half2_rn(c.y, s.y);
    __half2 h2 = __floats2half2_rn(c.z, s.z);
    __half2 h3 = __floats2half2_rn(c.w, s.w);
    uint4 o;
    o.x = *reinterpret_cast<unsigned*>(&h0);
    o.y = *reinterpret_cast<unsigned*>(&h1);
    o.z = *reinterpret_cast<unsigned*>(&h2);
    o.w = *reinterpret_cast<unsigned*>(&h3);
    *reinterpret_cast<uint4*>(&g_Wt[(size_t)j * KTOT + i * 64 + a * 8]) = o;
}

// ---------------------------------------------------------------------------
// Main kernel: 256 threads, grid (ISPLIT, Mtiles, Ntiles), 3 CTAs/SM.
// ---------------------------------------------------------------------------
__global__ void __launch_bounds__(256, 3) fkan_main_kernel(const float* __restrict__ x) {
    extern __shared__ char sm[];

    const int tid  = threadIdx.x;
    const int lane = tid & 31;
    const int wid  = tid >> 5;
    const int ks   = blockIdx.x;
    const int m0   = blockIdx.y * BM;
    const int n0   = blockIdx.z * BN;
    const int i_begin = ks * IPER;

    const int warp_m = (wid & 3) * 32;
    const int warp_n = (wid >> 2) * 32;

    char* aPtr[2] = { sm + OFF_A0, sm + OFF_A1 };
    const unsigned aU32[2] = { sptr(sm + OFF_A0), sptr(sm + OFF_A1) };
    const unsigned bU32[2] = { sptr(sm + OFF_B0), sptr(sm + OFF_B1) };

    float acc[2][4][4];
#pragma unroll
    for (int a = 0; a < 2; ++a)
#pragma unroll
        for (int b = 0; b < 4; ++b)
#pragma unroll
            for (int c = 0; c < 4; ++c) acc[a][b][c] = 0.0f;

    // ---- feature-gen role: 2 threads/row ----
    const int grow = tid >> 1;          // row 0..127
    const int gp   = tid & 1;           // g parity (start mult 1 or 2)
    const float* xsrc = x + (size_t)(m0 + grow) * IN_DIM + i_begin;

    // ---- B load role: 4 threads/row (64 rows x 128B) ----
    const int bj  = tid >> 2;           // 0..63
    const int bsg = tid & 3;            // 32B segment
    const __half* bsrc = g_Wt + (size_t)(n0 + bj) * KTOT + i_begin * 64 + bsg * 16;

    // ldmatrix byte offsets
    const int sel = lane >> 3;
    const int rr  = lane & 7;
    unsigned aOff[2];
#pragma unroll
    for (int mf = 0; mf < 2; ++mf)
        aOff[mf] = (unsigned)((warp_m + mf * 16 + (sel & 1) * 8 + rr) * LDRB
                              + (sel >> 1) * 16);
    unsigned bOff[2];
#pragma unroll
    for (int q = 0; q < 2; ++q)
        bOff[q] = (unsigned)((warp_n + q * 16 + (sel >> 1) * 8 + rr) * LDRB
                             + (sel & 1) * 16);

    auto loadB = [&](int buf, int ii) {
        const __half* s = bsrc + ii * 64;
        unsigned d = bU32[buf] + (unsigned)(bj * LDRB + bsg * 32);
        CP_ASYNC16(d,      s);
        CP_ASYNC16(d + 16, s + 8);
    };

    auto genA = [&](int buf, int ii) {
        float xv = __ldg(xsrc + ii);
        float s1, c1;
        sincosf(xv, &s1, &c1);
        float c2 = __fmaf_rn(2.f * c1, c1, -1.f);   // cos 2x
        float s2 = 2.f * s1 * c1;                   // sin 2x
        float ck = gp ? c2 : c1;                    // start mult = gp+1
        float sk = gp ? s2 : s1;
        __half* arow = reinterpret_cast<__half*>(aPtr[buf] + grow * LDRB) + 2 * gp;
#pragma unroll
        for (int n = 0; n < 16; ++n) {              // mult = gp+1 + 2n
            __half2 v = __floats2half2_rn(ck, sk);
            *reinterpret_cast<__half2*>(arow + 4 * n) = v;
            float nc = ck * c2 - sk * s2;
            float ns = sk * c2 + ck * s2;
            ck = nc; sk = ns;
        }
    };

    // ---- prologue ----
    loadB(0, 0);
    CP_COMMIT();
    genA(0, 0);
    CP_WAIT0();
    __syncthreads();

    // ---- main loop ----
    for (int ii = 0; ii < IPER; ++ii) {
        const int cur = ii & 1;
        const int nxt = cur ^ 1;

        if (ii + 1 < IPER) {
            loadB(nxt, ii + 1);
            CP_COMMIT();
            genA(nxt, ii + 1);
        }

        // kk loop with B-fragment register double buffering
        unsigned bf[2][2][4];
#pragma unroll
        for (int q = 0; q < 2; ++q) ldsm_x4(bf[0][q], bU32[cur] + bOff[q]);

#pragma unroll
        for (int kk = 0; kk < 4; ++kk) {
            const int cb = kk & 1, nb = cb ^ 1;
            unsigned af[2][4];
#pragma unroll
            for (int mf = 0; mf < 2; ++mf)
                ldsm_x4(af[mf], aU32[cur] + aOff[mf] + kk * 32);
            if (kk < 3) {
#pragma unroll
                for (int q = 0; q < 2; ++q)
                    ldsm_x4(bf[nb][q], bU32[cur] + bOff[q] + (kk + 1) * 32);
            }
#pragma unroll
            for (int mf = 0; mf < 2; ++mf)
#pragma unroll
                for (int q = 0; q < 2; ++q) {
                    mma16816(acc[mf][2 * q],     af[mf], &bf[cb][q][0]);
                    mma16816(acc[mf][2 * q + 1], af[mf], &bf[cb][q][2]);
                }
        }

        CP_WAIT0();
        __syncthreads();
    }

    // ---- epilogue: store split-K partials ----
    {
        float* base = g_part + (size_t)ks * M_MAX * OUT_DIM;
#pragma unroll
        for (int mf = 0; mf < 2; ++mf) {
            int r0 = m0 + warp_m + mf * 16 + (lane >> 2);
#pragma unroll
            for (int nf = 0; nf < 4; ++nf) {
                int cidx = n0 + warp_n + nf * 8 + ((lane & 3) << 1);
                float2 v0 = { acc[mf][nf][0], acc[mf][nf][1] };
                float2 v1 = { acc[mf][nf][2], acc[mf][nf][3] };
                *reinterpret_cast<float2*>(base + (size_t)r0 * OUT_DIM + cidx)       = v0;
                *reinterpret_cast<float2*>(base + (size_t)(r0 + 8) * OUT_DIM + cidx) = v1;
            }
        }
    }
}

// ---------------------------------------------------------------------------
// Reduce: out = sum over 8 splits + bias
// ---------------------------------------------------------------------------
__global__ void __launch_bounds__(256) reduce_kernel(const float* __restrict__ bias,
                                                     float* __restrict__ out, int total4) {
    int i = blockIdx.x * blockDim.x + threadIdx.x;
    if (i >= total4) return;
    const int S = M_MAX * OUT_DIM / 4;
    const float4* p = reinterpret_cast<const float4*>(g_part);
    float4 bb = reinterpret_cast<const float4*>(bias)[i & 63];
    float4 o = bb;
#pragma unroll
    for (int s = 0; s < ISPLIT; ++s) {
        float4 v = p[i + s * S];
        o.x += v.x; o.y += v.y; o.z += v.z; o.w += v.w;
    }
    reinterpret_cast<float4*>(out)[i] = o;
}

// Pads so ncu's absolute capture index 3 lands on fkan_main_kernel.
__global__ void nop_kernel() {}

extern "C" void kernel_launch(void* const* d_in, const int* in_sizes, int n_in,
                              void* d_out, int out_size) {
    const float* x      = (const float*)d_in[0];   // [M, 256]
    const float* coeffs = (const float*)d_in[1];   // [2, 256, 256, 32]
    const float* bias   = (const float*)d_in[2];   // [1, 256]
    float* out = (float*)d_out;

    int Mrows = in_sizes[0] / IN_DIM;              // 4096

    cudaFuncSetAttribute(fkan_main_kernel,
                         cudaFuncAttributeMaxDynamicSharedMemorySize, SMEM_BYTES);

    prep_coeffs_kernel<<<(1 << 19) / 256, 256>>>(coeffs);   // idx 0
    nop_kernel<<<1, 1>>>();                                 // idx 1
    nop_kernel<<<1, 1>>>();                                 // idx 2

    dim3 grid(ISPLIT, Mrows / BM, OUT_DIM / BN);   // (8, 32, 4) = 1024 CTAs
    fkan_main_kernel<<<grid, 256, SMEM_BYTES>>>(x); // idx 3  <- ncu capture

    int total4 = Mrows * OUT_DIM / 4;
    reduce_kernel<<<(total4 + 255) / 256, 256>>>(bias, out, total4);
}

// round 11
// speedup vs baseline: 1.1270x; 1.1270x over previous
#include <cuda_runtime.h>
#include <cuda_fp16.h>
#include <cstdint>

// FourierKAN fused feature-gen + mma.sync fp16 GEMM (compute_103-safe).
// y[b,j] = sum_{i,g} cos((g+1)x_bi)C0[j,i,g] + sin((g+1)x_bi)C1[j,i,g] + bias[j]
// k layout: k = i*64 + 2*g + trig  (even k = cos, odd k = sin)
// CTA tile 128x128, 8 warps (2m x 4n), warp 64x32, split-K x4, 2 CTAs/SM.
// (R5 optimum config; genA with contiguous-g chains + STS.128.)

#define IN_DIM   256
#define OUT_DIM  256
#define KTOT     (IN_DIM * 64)
#define BM       128
#define BN       128
#define ISPLIT   4
#define IPER     (IN_DIM / ISPLIT)   // 64
#define M_MAX    4096

#define LDRB     144                 // 72-half row stride: 16B aligned, LDSM conflict-free

#define OFF_A0   0
#define OFF_A1   18432
#define OFF_B0   36864
#define OFF_B1   55296
#define SMEM_BYTES 73728             // 72 KB -> 2 CTAs/SM

__device__ __half g_Wt[OUT_DIM * KTOT];              // 8.4 MB (L2-resident)
__device__ float  g_part[ISPLIT * M_MAX * OUT_DIM];  // 16 MB split-K partials

__device__ __forceinline__ unsigned sptr(const void* p) {
    return (unsigned)__cvta_generic_to_shared(p);
}

#define CP_ASYNC16(dst, src) \
    asm volatile("cp.async.cg.shared.global [%0], [%1], 16;\n" :: "r"(dst), "l"(src))
#define CP_COMMIT() asm volatile("cp.async.commit_group;\n" ::)
#define CP_WAIT0()  asm volatile("cp.async.wait_group 0;\n" ::)

__device__ __forceinline__ void mma16816(float c[4], const unsigned a[4], const unsigned* b) {
    asm volatile(
        "mma.sync.aligned.m16n8k16.row.col.f32.f16.f16.f32 "
        "{%0,%1,%2,%3}, {%4,%5,%6,%7}, {%8,%9}, {%0,%1,%2,%3};\n"
        : "+f"(c[0]), "+f"(c[1]), "+f"(c[2]), "+f"(c[3])
        : "r"(a[0]), "r"(a[1]), "r"(a[2]), "r"(a[3]), "r"(b[0]), "r"(b[1]));
}
__device__ __forceinline__ void ldsm_x4(unsigned r[4], unsigned addr) {
    asm volatile("ldmatrix.sync.aligned.m8n8.x4.shared.b16 {%0,%1,%2,%3}, [%4];\n"
                 : "=r"(r[0]), "=r"(r[1]), "=r"(r[2]), "=r"(r[3]) : "r"(addr));
}

// ---------------------------------------------------------------------------
// Prep: coeffs fp32 [2][out][in][grid] -> fp16 g_Wt[j][i*64 + 2g + trig]
// ---------------------------------------------------------------------------
__global__ void __launch_bounds__(256) prep_coeffs_kernel(const float* __restrict__ C) {
    unsigned u = blockIdx.x * blockDim.x + threadIdx.x;   // 0 .. 2^19-1
    const float4* C4 = reinterpret_cast<const float4*>(C);
    float4 c = C4[u];                 // cos coeffs, g = 4a..4a+3
    float4 s = C4[u + (1u << 19)];    // sin coeffs
    unsigned a = u & 7, i = (u >> 3) & 255, j = u >> 11;
    __half2 h0 = __floats2half2_rn(c.x, s.x);
    __half2 h1 = __floats2half2_rn(c.y, s.y);
    __half2 h2 = __floats2half2_rn(c.z, s.z);
    __half2 h3 = __floats2half2_rn(c.w, s.w);
    uint4 o;
    o.x = *reinterpret_cast<unsigned*>(&h0);
    o.y = *reinterpret_cast<unsigned*>(&h1);
    o.z = *reinterpret_cast<unsigned*>(&h2);
    o.w = *reinterpret_cast<unsigned*>(&h3);
    *reinterpret_cast<uint4*>(&g_Wt[(size_t)j * KTOT + i * 64 + a * 8]) = o;
}

// ---------------------------------------------------------------------------
// Main kernel: 256 threads, grid (ISPLIT, Mtiles, Ntiles), 2 CTAs/SM.
// ---------------------------------------------------------------------------
__global__ void __launch_bounds__(256, 2) fkan_main_kernel(const float* __restrict__ x) {
    extern __shared__ char sm[];

    const int tid  = threadIdx.x;
    const int lane = tid & 31;
    const int wid  = tid >> 5;
    const int ks   = blockIdx.x;
    const int m0   = blockIdx.y * BM;
    const int n0   = blockIdx.z * BN;
    const int i_begin = ks * IPER;

    const int warp_m = (wid & 1) * 64;
    const int warp_n = (wid >> 1) * 32;

    char* aPtr[2] = { sm + OFF_A0, sm + OFF_A1 };
    const unsigned aU32[2] = { sptr(sm + OFF_A0), sptr(sm + OFF_A1) };
    const unsigned bU32[2] = { sptr(sm + OFF_B0), sptr(sm + OFF_B1) };

    float acc[4][4][4];
#pragma unroll
    for (int a = 0; a < 4; ++a)
#pragma unroll
        for (int b = 0; b < 4; ++b)
#pragma unroll
            for (int c = 0; c < 4; ++c) acc[a][b][c] = 0.0f;

    // ---- feature-gen role: 2 threads/row, thread gt owns g in [16*gt, 16*gt+16) ----
    const int grow = tid >> 1;          // row 0..127
    const int gt   = tid & 1;           // g-half selector
    const float* xsrc = x + (size_t)(m0 + grow) * IN_DIM + i_begin;

    // ---- B load role: 2 threads/row ----
    const int bj = tid >> 1;            // 0..127
    const int bh = tid & 1;             // 64B half
    const __half* bsrc = g_Wt + (size_t)(n0 + bj) * KTOT + i_begin * 64 + bh * 32;

    // ldmatrix byte offsets
    const int sel = lane >> 3;
    const int rr  = lane & 7;
    unsigned aOff[4];
#pragma unroll
    for (int mf = 0; mf < 4; ++mf)
        aOff[mf] = (unsigned)((warp_m + mf * 16 + (sel & 1) * 8 + rr) * LDRB
                              + (sel >> 1) * 16);
    unsigned bOff[2];
#pragma unroll
    for (int q = 0; q < 2; ++q)
        bOff[q] = (unsigned)((warp_n + q * 16 + (sel >> 1) * 8 + rr) * LDRB
                             + (sel & 1) * 16);

    auto loadB = [&](int buf, int ii) {
        const __half* s = bsrc + ii * 64;
        unsigned d = bU32[buf] + (unsigned)(bj * LDRB + bh * 64);
#pragma unroll
        for (int seg = 0; seg < 4; ++seg)
            CP_ASYNC16(d + seg * 16, s + seg * 8);
    };

    // contiguous-g chain: start mult = 16*gt + 1, step-1 rotation by e^{ix}.
    auto genA = [&](int buf, int ii) {
        float xv = __ldg(xsrc + ii);
        float s1, c1;
        sincosf(xv, &s1, &c1);
        // e^{i16x} via 4 doublings (always computed; selected by gt)
        float c2  = __fmaf_rn(2.f * c1, c1, -1.f),  s2  = 2.f * s1 * c1;
        float c4  = __fmaf_rn(2.f * c2, c2, -1.f),  s4  = 2.f * s2 * c2;
        float c8  = __fmaf_rn(2.f * c4, c4, -1.f),  s8  = 2.f * s4 * c4;
        float c16 = __fmaf_rn(2.f * c8, c8, -1.f),  s16 = 2.f * s8 * c8;
        float c17 = c16 * c1 - s16 * s1;
        float s17 = s16 * c1 + c16 * s1;
        float ck = gt ? c17 : c1;   // mult = 16*gt + 1
        float sk = gt ? s17 : s1;
        __half2 vb[16];
#pragma unroll
        for (int n = 0; n < 16; ++n) {          // mult = 16*gt + 1 + n
            vb[n] = __floats2half2_rn(ck, sk);
            float nc = ck * c1 - sk * s1;
            float ns = sk * c1 + ck * s1;
            ck = nc; sk = ns;
        }
        uint4* dst = reinterpret_cast<uint4*>(aPtr[buf] + grow * LDRB + gt * 64);
        const uint4* srcv = reinterpret_cast<const uint4*>(vb);
        dst[0] = srcv[0];
        dst[1] = srcv[1];
        dst[2] = srcv[2];
        dst[3] = srcv[3];
    };

    // ---- prologue ----
    loadB(0, 0);
    CP_COMMIT();
    genA(0, 0);
    CP_WAIT0();
    __syncthreads();

    // ---- main loop ----
    for (int ii = 0; ii < IPER; ++ii) {
        const int cur = ii & 1;
        const int nxt = cur ^ 1;

        if (ii + 1 < IPER) {
            loadB(nxt, ii + 1);
            CP_COMMIT();
            genA(nxt, ii + 1);
        }

        // kk loop with B-fragment register double buffering
        unsigned bf[2][2][4];
#pragma unroll
        for (int q = 0; q < 2; ++q) ldsm_x4(bf[0][q], bU32[cur] + bOff[q]);

#pragma unroll
        for (int kk = 0; kk < 4; ++kk) {
            const int cb = kk & 1, nb = cb ^ 1;
            unsigned af[4][4];
#pragma unroll
            for (int mf = 0; mf < 4; ++mf)
                ldsm_x4(af[mf], aU32[cur] + aOff[mf] + kk * 32);
            if (kk < 3) {
#pragma unroll
                for (int q = 0; q < 2; ++q)
                    ldsm_x4(bf[nb][q], bU32[cur] + bOff[q] + (kk + 1) * 32);
            }
#pragma unroll
            for (int mf = 0; mf < 4; ++mf)
#pragma unroll
                for (int q = 0; q < 2; ++q) {
                    mma16816(acc[mf][2 * q],     af[mf], &bf[cb][q][0]);
                    mma16816(acc[mf][2 * q + 1], af[mf], &bf[cb][q][2]);
                }
        }

        CP_WAIT0();
        __syncthreads();
    }

    // ---- epilogue: store split-K partials ----
    {
        float* base = g_part + (size_t)ks * M_MAX * OUT_DIM;
#pragma unroll
        for (int mf = 0; mf < 4; ++mf) {
            int r0 = m0 + warp_m + mf * 16 + (lane >> 2);
#pragma unroll
            for (int nf = 0; nf < 4; ++nf) {
                int cidx = n0 + warp_n + nf * 8 + ((lane & 3) << 1);
                float2 v0 = { acc[mf][nf][0], acc[mf][nf][1] };
                float2 v1 = { acc[mf][nf][2], acc[mf][nf][3] };
                *reinterpret_cast<float2*>(base + (size_t)r0 * OUT_DIM + cidx)       = v0;
                *reinterpret_cast<float2*>(base + (size_t)(r0 + 8) * OUT_DIM + cidx) = v1;
            }
        }
    }
}

// ---------------------------------------------------------------------------
// Reduce: out = sum over 4 splits + bias
// ---------------------------------------------------------------------------
__global__ void __launch_bounds__(256) reduce_kernel(const float* __restrict__ bias,
                                                     float* __restrict__ out, int total4) {
    int i = blockIdx.x * blockDim.x + threadIdx.x;
    if (i >= total4) return;
    const int S = M_MAX * OUT_DIM / 4;
    const float4* p = reinterpret_cast<const float4*>(g_part);
    float4 a = p[i], b = p[i + S], c = p[i + 2 * S], d = p[i + 3 * S];
    float4 bb = reinterpret_cast<const float4*>(bias)[i & 63];
    float4 o;
    o.x = a.x + b.x + c.x + d.x + bb.x;
    o.y = a.y + b.y + c.y + d.y + bb.y;
    o.z = a.z + b.z + c.z + d.z + bb.z;
    o.w = a.w + b.w + c.w + d.w + bb.w;
    reinterpret_cast<float4*>(out)[i] = o;
}

extern "C" void kernel_launch(void* const* d_in, const int* in_sizes, int n_in,
                              void* d_out, int out_size) {
    const float* x      = (const float*)d_in[0];   // [M, 256]
    const float* coeffs = (const float*)d_in[1];   // [2, 256, 256, 32]
    const float* bias   = (const float*)d_in[2];   // [1, 256]
    float* out = (float*)d_out;

    int Mrows = in_sizes[0] / IN_DIM;              // 4096

    cudaFuncSetAttribute(fkan_main_kernel,
                         cudaFuncAttributeMaxDynamicSharedMemorySize, SMEM_BYTES);

    prep_coeffs_kernel<<<(1 << 19) / 256, 256>>>(coeffs);

    dim3 grid(ISPLIT, Mrows / BM, OUT_DIM / BN);   // (4, 32, 2) = 256 CTAs
    fkan_main_kernel<<<grid, 256, SMEM_BYTES>>>(x);

    int total4 = Mrows * OUT_DIM / 4;
    reduce_kernel<<<(total4 + 255) / 256, 256>>>(bias, out, total4);
}